// round 7
// baseline (speedup 1.0000x reference)
#include <cuda_runtime.h>

// R6 = re-bench of R4 candidate (R5 failed with a device-acquisition infra
// error before launch; the grid-emulation fix was never tested).

// Problem constants
constexpr int TOK   = 32768;        // B*N
constexpr int D     = 1024;
constexpr int S     = 4;
constexpr int DSUB  = 256;          // D/S
constexpr int K     = 16;
constexpr int ZSIZE = TOK * D;      // 33554432 floats of z
constexpr int IDOFF = ZSIZE;        // ids at [ZSIZE, ZSIZE+TOK)
constexpr int VQOFF = ZSIZE + TOK;  // scalar at the end
constexpr int NB    = 304;          // persistent grid (2 blocks/SM on 152 SMs)

#define FULL 0xFFFFFFFFu

__device__ float g_vq_accum;

// ---- packed f32x2 helpers (sm_103a FFMA2 path) ----
static __device__ __forceinline__ unsigned long long pk2(float x, float y) {
    unsigned long long r;
    asm("mov.b64 %0, {%1, %2};" : "=l"(r) : "f"(x), "f"(y));
    return r;
}
static __device__ __forceinline__ void upk2(unsigned long long v, float& x, float& y) {
    asm("mov.b64 {%0, %1}, %2;" : "=f"(x), "=f"(y) : "l"(v));
}
static __device__ __forceinline__ unsigned long long ffma2(
    unsigned long long a, unsigned long long b, unsigned long long c) {
    unsigned long long d;
    asm("fma.rn.f32x2 %0, %1, %2, %3;" : "=l"(d) : "l"(a), "l"(b), "l"(c));
    return d;
}

__global__ void dvq_init_kernel() { g_vq_accum = 0.0f; }

__global__ void dvq_fin_kernel(float* out) {
    // vq_total = (1 + BETA) * sum_sq / (B*N*d) ; BETA=0.25, B*N*d = 8388608
    out[VQOFF] = g_vq_accum * (1.25f / 8388608.0f);
}

__global__ __launch_bounds__(128) void dvq_kernel(
    const float* __restrict__ h, const float* __restrict__ cb,
    float* __restrict__ out, int nblocks)
{
    extern __shared__ float cb_sm[];            // [S][K][DSUB] = 16384 floats = 64 KB
    __shared__ int codes_sm[2][4];

    const int tid = threadIdx.x;
    const int w   = tid >> 5;                   // warp index == subspace
    const int L   = tid & 31;
    const int s   = w;

    // Cooperative load of all codebooks into SMEM (one-time per block)
    {
        const float4* cbg = (const float4*)cb;
        float4* cbs = (float4*)cb_sm;
        for (int i = tid; i < S * K * DSUB / 4; i += 128) cbs[i] = cbg[i];
    }
    __syncthreads();

    const float* cbws = cb_sm + s * K * DSUB;

    // Register-resident codebook: lane L owns elems [8L, 8L+8) of every code.
    unsigned long long cbr[K][4];
    #pragma unroll
    for (int k = 0; k < K; k++) {
        float4 a = *(const float4*)(cbws + k * DSUB + L * 8);
        float4 b = *(const float4*)(cbws + k * DSUB + L * 8 + 4);
        cbr[k][0] = pk2(a.x, a.y); cbr[k][1] = pk2(a.z, a.w);
        cbr[k][2] = pk2(b.x, b.y); cbr[k][3] = pk2(b.z, b.w);
    }

    // After the multi-value butterfly, lane L holds the dot for code bitrev4(L&15).
    const int myCode = ((L >> 3) & 1) | ((L >> 1) & 2) | ((L << 1) & 4) | ((L << 3) & 8);
    // ||cb_myCode||^2, computed in fp64 then rounded to fp32 (closest proxy to
    // the reference's (codebooks**2).sum(-1) value; its exact low bits set
    // rounding boundaries in the fp32 grid emulation below).
    float myCsq;
    {
        const float* c = cbws + myCode * DSUB;
        double acc = 0.0;
        for (int j = 0; j < DSUB; j++) acc = fma((double)c[j], (double)c[j], acc);
        myCsq = (float)acc;
    }

    float errAcc = 0.0f;

    int t = blockIdx.x;
    // 1-token-deep register prefetch of ze
    float4 pfA, pfB;
    if (t < TOK) {
        const float4* p = (const float4*)(h + (size_t)t * D + s * DSUB + L * 8);
        pfA = p[0]; pfB = p[1];
    }

    int it = 0;
    for (; t < TOK; t += nblocks, it++) {
        const float4 curA = pfA, curB = pfB;
        const int tn = t + nblocks;
        if (tn < TOK) {
            const float4* p = (const float4*)(h + (size_t)tn * D + s * DSUB + L * 8);
            pfA = p[0]; pfB = p[1];
        }

        unsigned long long ze2[4];
        ze2[0] = pk2(curA.x, curA.y); ze2[1] = pk2(curA.z, curA.w);
        ze2[2] = pk2(curB.x, curB.y); ze2[3] = pk2(curB.z, curB.w);

        // ||ze||^2 (identical bit pattern on all 32 lanes: commutative butterfly)
        unsigned long long za = 0ull;
        #pragma unroll
        for (int j = 0; j < 4; j++) za = ffma2(ze2[j], ze2[j], za);
        float zx, zy; upk2(za, zx, zy);
        float zs = zx + zy;
        #pragma unroll
        for (int m = 16; m >= 1; m >>= 1) zs += __shfl_xor_sync(FULL, zs, m);

        // Per-lane partial dots for all 16 codes (packed f32x2 FMAs)
        float v[16];
        #pragma unroll
        for (int k = 0; k < 16; k++) {
            unsigned long long acc = 0ull;   // (+0.f, +0.f)
            #pragma unroll
            for (int j = 0; j < 4; j++) acc = ffma2(ze2[j], cbr[k][j], acc);
            float x, y; upk2(acc, x, y);
            v[k] = x + y;
        }

        // Multi-value butterfly: 16 values over 16 lanes in 15 shuffles
        {   // mask 1, half 8
            const bool lo = (L & 1) == 0;
            #pragma unroll
            for (int i = 0; i < 8; i++) {
                float snd = lo ? v[i + 8] : v[i];
                float rcv = __shfl_xor_sync(FULL, snd, 1);
                v[i] = (lo ? v[i] : v[i + 8]) + rcv;
            }
        }
        {   // mask 2, half 4
            const bool lo = (L & 2) == 0;
            #pragma unroll
            for (int i = 0; i < 4; i++) {
                float snd = lo ? v[i + 4] : v[i];
                float rcv = __shfl_xor_sync(FULL, snd, 2);
                v[i] = (lo ? v[i] : v[i + 4]) + rcv;
            }
        }
        {   // mask 4, half 2
            const bool lo = (L & 4) == 0;
            #pragma unroll
            for (int i = 0; i < 2; i++) {
                float snd = lo ? v[i + 2] : v[i];
                float rcv = __shfl_xor_sync(FULL, snd, 4);
                v[i] = (lo ? v[i] : v[i + 2]) + rcv;
            }
        }
        {   // mask 8, half 1
            const bool lo = (L & 8) == 0;
            float snd = lo ? v[1] : v[0];
            float rcv = __shfl_xor_sync(FULL, snd, 8);
            v[0] = (lo ? v[0] : v[1]) + rcv;
        }
        // fold the two 16-lane halves
        const float dot = v[0] + __shfl_xor_sync(FULL, v[0], 16);

        // ---- fp32 grid emulation of the reference's distance ----
        // ref: dist = fl32( fl32(zsq + csq_k) - fl32(2*dot_k) ); 2*dot exact.
        // The coarse grid (ulp ~3e-5 at dist~256) collapses near-ties exactly
        // like XLA; argmin then breaks exact ties toward the lower index.
        const float A    = __fadd_rn(zs, myCsq);
        float dist = __fsub_rn(A, 2.0f * dot);
        int   kc   = myCode;
        #pragma unroll
        for (int m = 1; m <= 8; m <<= 1) {
            float od = __shfl_xor_sync(FULL, dist, m);
            int   oc = __shfl_xor_sync(FULL, kc, m);
            bool take = (od < dist) || (od == dist && oc < kc);
            if (take) { dist = od; kc = oc; }
        }
        const int kmin = kc;   // identical across all 32 lanes

        // gather zq from SMEM (dynamic code index)
        const float* zqp = cbws + kmin * DSUB + L * 8;
        const float4 qA = *(const float4*)zqp;
        const float4 qB = *(const float4*)(zqp + 4);

        // loss accumulation: sum (zq - ze)^2
        float e, dx;
        dx = qA.x - curA.x; e = dx * dx;
        dx = qA.y - curA.y; e = fmaf(dx, dx, e);
        dx = qA.z - curA.z; e = fmaf(dx, dx, e);
        dx = qA.w - curA.w; e = fmaf(dx, dx, e);
        dx = qB.x - curB.x; e = fmaf(dx, dx, e);
        dx = qB.y - curB.y; e = fmaf(dx, dx, e);
        dx = qB.z - curB.z; e = fmaf(dx, dx, e);
        dx = qB.w - curB.w; e = fmaf(dx, dx, e);
        errAcc += e;

        // z output: reference computes z = fl(ze + fl(zq - ze)), which is NOT
        // bit-identical to zq. Emulate it exactly.
        float4 oA, oB;
        oA.x = __fadd_rn(curA.x, __fsub_rn(qA.x, curA.x));
        oA.y = __fadd_rn(curA.y, __fsub_rn(qA.y, curA.y));
        oA.z = __fadd_rn(curA.z, __fsub_rn(qA.z, curA.z));
        oA.w = __fadd_rn(curA.w, __fsub_rn(qA.w, curA.w));
        oB.x = __fadd_rn(curB.x, __fsub_rn(qB.x, curB.x));
        oB.y = __fadd_rn(curB.y, __fsub_rn(qB.y, curB.y));
        oB.z = __fadd_rn(curB.z, __fsub_rn(qB.z, curB.z));
        oB.w = __fadd_rn(curB.w, __fsub_rn(qB.w, curB.w));
        float4* zo = (float4*)(out + (size_t)t * D + s * DSUB + L * 8);
        zo[0] = oA; zo[1] = oB;

        // combine the 4 subspace codes -> packed id (double-buffered SMEM)
        if (L == 0) codes_sm[it & 1][w] = kmin;
        __syncthreads();
        if (tid == 0) {
            const int* c = codes_sm[it & 1];
            int packed = c[0] + 16 * c[1] + 256 * c[2] + 4096 * c[3];
            out[IDOFF + t] = (float)packed;
        }
    }

    // reduce loss within warp, one atomic per warp
    #pragma unroll
    for (int m = 16; m >= 1; m >>= 1) errAcc += __shfl_xor_sync(FULL, errAcc, m);
    if (L == 0) atomicAdd(&g_vq_accum, errAcc);
}

extern "C" void kernel_launch(void* const* d_in, const int* in_sizes, int n_in,
                              void* d_out, int out_size) {
    const float* h  = (const float*)d_in[0];
    const float* cb = (const float*)d_in[1];
    float* out = (float*)d_out;

    cudaFuncSetAttribute(dvq_kernel, cudaFuncAttributeMaxDynamicSharedMemorySize, 65536);

    dvq_init_kernel<<<1, 1>>>();
    dvq_kernel<<<NB, 128, 65536>>>(h, cb, out, NB);
    dvq_fin_kernel<<<1, 1>>>(out);
}

// round 8
// speedup vs baseline: 1.1223x; 1.1223x over previous
#include <cuda_runtime.h>

// R8: perf pass on the R6/R7-passing kernel (154.1us, rel_err 4.8e-7).
// Numerics (fp32 grid emulation of reference distance + z = fl(ze+fl(zq-ze)))
// are unchanged. Changes: no per-iteration __syncthreads (ids via scratch +
// pack kernel), prefetch depth 3, streaming cache hints, no init kernel.

// Problem constants
constexpr int TOK   = 32768;        // B*N
constexpr int D     = 1024;
constexpr int S     = 4;
constexpr int DSUB  = 256;          // D/S
constexpr int K     = 16;
constexpr int ZSIZE = TOK * D;      // 33554432 floats of z
constexpr int IDOFF = ZSIZE;        // ids at [ZSIZE, ZSIZE+TOK)
constexpr int VQOFF = ZSIZE + TOK;  // scalar at the end
constexpr int NB    = 304;          // persistent grid (2 blocks/SM on 152 SMs)

#define FULL 0xFFFFFFFFu

__device__ int   g_codes[S][TOK];     // per-subspace argmin codes (scratch)
__device__ float g_partials[NB * 4];  // per-warp loss partial sums

// ---- packed f32x2 helpers (sm_103a FFMA2 path) ----
static __device__ __forceinline__ unsigned long long pk2(float x, float y) {
    unsigned long long r;
    asm("mov.b64 %0, {%1, %2};" : "=l"(r) : "f"(x), "f"(y));
    return r;
}
static __device__ __forceinline__ void upk2(unsigned long long v, float& x, float& y) {
    asm("mov.b64 {%0, %1}, %2;" : "=f"(x), "=f"(y) : "l"(v));
}
static __device__ __forceinline__ unsigned long long ffma2(
    unsigned long long a, unsigned long long b, unsigned long long c) {
    unsigned long long d;
    asm("fma.rn.f32x2 %0, %1, %2, %3;" : "=l"(d) : "l"(a), "l"(b), "l"(c));
    return d;
}

__global__ __launch_bounds__(128) void dvq_kernel(
    const float* __restrict__ h, const float* __restrict__ cb,
    float* __restrict__ out, int nblocks)
{
    extern __shared__ float cb_sm[];            // [S][K][DSUB] = 64 KB

    const int tid = threadIdx.x;
    const int w   = tid >> 5;                   // warp index == subspace
    const int L   = tid & 31;
    const int s   = w;

    // Cooperative load of all codebooks into SMEM (one-time per block)
    {
        const float4* cbg = (const float4*)cb;
        float4* cbs = (float4*)cb_sm;
        for (int i = tid; i < S * K * DSUB / 4; i += 128) cbs[i] = cbg[i];
    }
    __syncthreads();

    const float* cbws = cb_sm + s * K * DSUB;

    // Register-resident codebook: lane L owns elems [8L, 8L+8) of every code.
    unsigned long long cbr[K][4];
    #pragma unroll
    for (int k = 0; k < K; k++) {
        float4 a = *(const float4*)(cbws + k * DSUB + L * 8);
        float4 b = *(const float4*)(cbws + k * DSUB + L * 8 + 4);
        cbr[k][0] = pk2(a.x, a.y); cbr[k][1] = pk2(a.z, a.w);
        cbr[k][2] = pk2(b.x, b.y); cbr[k][3] = pk2(b.z, b.w);
    }

    // After the multi-value butterfly, lane L holds the dot for code bitrev4(L&15).
    const int myCode = ((L >> 3) & 1) | ((L >> 1) & 2) | ((L << 1) & 4) | ((L << 3) & 8);
    // ||cb_myCode||^2 in fp64, rounded to fp32 (proxy for the reference's
    // (codebooks**2).sum(-1); its low bits set grid-rounding boundaries).
    float myCsq;
    {
        const float* c = cbws + myCode * DSUB;
        double acc = 0.0;
        for (int j = 0; j < DSUB; j++) acc = fma((double)c[j], (double)c[j], acc);
        myCsq = (float)acc;
    }

    float errAcc = 0.0f;

    // ---- 3-deep register prefetch of ze (streaming loads) ----
    const int lofs = s * DSUB + L * 8;
    int t = blockIdx.x;
    float4 p0A, p0B, p1A, p1B, p2A, p2B;
    {
        const float4* p = (const float4*)(h + (size_t)t * D + lofs);
        p0A = __ldcs(p); p0B = __ldcs(p + 1);
    }
    if (t + nblocks < TOK) {
        const float4* p = (const float4*)(h + (size_t)(t + nblocks) * D + lofs);
        p1A = __ldcs(p); p1B = __ldcs(p + 1);
    }
    if (t + 2 * nblocks < TOK) {
        const float4* p = (const float4*)(h + (size_t)(t + 2 * nblocks) * D + lofs);
        p2A = __ldcs(p); p2B = __ldcs(p + 1);
    }

    for (; t < TOK; t += nblocks) {
        const float4 curA = p0A, curB = p0B;
        p0A = p1A; p0B = p1B;
        p1A = p2A; p1B = p2B;
        const int tn = t + 3 * nblocks;
        if (tn < TOK) {
            const float4* p = (const float4*)(h + (size_t)tn * D + lofs);
            p2A = __ldcs(p); p2B = __ldcs(p + 1);
        }

        unsigned long long ze2[4];
        ze2[0] = pk2(curA.x, curA.y); ze2[1] = pk2(curA.z, curA.w);
        ze2[2] = pk2(curB.x, curB.y); ze2[3] = pk2(curB.z, curB.w);

        // ||ze||^2 (identical bit pattern on all 32 lanes: commutative butterfly)
        unsigned long long za = 0ull;
        #pragma unroll
        for (int j = 0; j < 4; j++) za = ffma2(ze2[j], ze2[j], za);
        float zx, zy; upk2(za, zx, zy);
        float zs = zx + zy;
        #pragma unroll
        for (int m = 16; m >= 1; m >>= 1) zs += __shfl_xor_sync(FULL, zs, m);

        // Per-lane partial dots for all 16 codes (packed f32x2 FMAs)
        float v[16];
        #pragma unroll
        for (int k = 0; k < 16; k++) {
            unsigned long long acc = 0ull;   // (+0.f, +0.f)
            #pragma unroll
            for (int j = 0; j < 4; j++) acc = ffma2(ze2[j], cbr[k][j], acc);
            float x, y; upk2(acc, x, y);
            v[k] = x + y;
        }

        // Multi-value butterfly: 16 values over 16 lanes in 15 shuffles
        {   // mask 1, half 8
            const bool lo = (L & 1) == 0;
            #pragma unroll
            for (int i = 0; i < 8; i++) {
                float snd = lo ? v[i + 8] : v[i];
                float rcv = __shfl_xor_sync(FULL, snd, 1);
                v[i] = (lo ? v[i] : v[i + 8]) + rcv;
            }
        }
        {   // mask 2, half 4
            const bool lo = (L & 2) == 0;
            #pragma unroll
            for (int i = 0; i < 4; i++) {
                float snd = lo ? v[i + 4] : v[i];
                float rcv = __shfl_xor_sync(FULL, snd, 2);
                v[i] = (lo ? v[i] : v[i + 4]) + rcv;
            }
        }
        {   // mask 4, half 2
            const bool lo = (L & 4) == 0;
            #pragma unroll
            for (int i = 0; i < 2; i++) {
                float snd = lo ? v[i + 2] : v[i];
                float rcv = __shfl_xor_sync(FULL, snd, 4);
                v[i] = (lo ? v[i] : v[i + 2]) + rcv;
            }
        }
        {   // mask 8, half 1
            const bool lo = (L & 8) == 0;
            float snd = lo ? v[1] : v[0];
            float rcv = __shfl_xor_sync(FULL, snd, 8);
            v[0] = (lo ? v[0] : v[1]) + rcv;
        }
        // fold the two 16-lane halves
        const float dot = v[0] + __shfl_xor_sync(FULL, v[0], 16);

        // ---- fp32 grid emulation of the reference's distance ----
        // ref: dist = fl32( fl32(zsq + csq_k) - fl32(2*dot_k) ); 2*dot exact.
        const float A    = __fadd_rn(zs, myCsq);
        float dist = __fsub_rn(A, 2.0f * dot);
        int   kc   = myCode;
        #pragma unroll
        for (int m = 1; m <= 8; m <<= 1) {
            float od = __shfl_xor_sync(FULL, dist, m);
            int   oc = __shfl_xor_sync(FULL, kc, m);
            bool take = (od < dist) || (od == dist && oc < kc);
            if (take) { dist = od; kc = oc; }
        }
        const int kmin = kc;   // identical across all 32 lanes

        // gather zq from SMEM (dynamic code index)
        const float* zqp = cbws + kmin * DSUB + L * 8;
        const float4 qA = *(const float4*)zqp;
        const float4 qB = *(const float4*)(zqp + 4);

        // loss accumulation: sum (zq - ze)^2
        float e, dx;
        dx = qA.x - curA.x; e = dx * dx;
        dx = qA.y - curA.y; e = fmaf(dx, dx, e);
        dx = qA.z - curA.z; e = fmaf(dx, dx, e);
        dx = qA.w - curA.w; e = fmaf(dx, dx, e);
        dx = qB.x - curB.x; e = fmaf(dx, dx, e);
        dx = qB.y - curB.y; e = fmaf(dx, dx, e);
        dx = qB.z - curB.z; e = fmaf(dx, dx, e);
        dx = qB.w - curB.w; e = fmaf(dx, dx, e);
        errAcc += e;

        // z output: reference computes z = fl(ze + fl(zq - ze)) — emulate exactly.
        float4 oA, oB;
        oA.x = __fadd_rn(curA.x, __fsub_rn(qA.x, curA.x));
        oA.y = __fadd_rn(curA.y, __fsub_rn(qA.y, curA.y));
        oA.z = __fadd_rn(curA.z, __fsub_rn(qA.z, curA.z));
        oA.w = __fadd_rn(curA.w, __fsub_rn(qA.w, curA.w));
        oB.x = __fadd_rn(curB.x, __fsub_rn(qB.x, curB.x));
        oB.y = __fadd_rn(curB.y, __fsub_rn(qB.y, curB.y));
        oB.z = __fadd_rn(curB.z, __fsub_rn(qB.z, curB.z));
        oB.w = __fadd_rn(curB.w, __fsub_rn(qB.w, curB.w));
        float4* zo = (float4*)(out + (size_t)t * D + lofs);
        __stcs(zo,     oA);
        __stcs(zo + 1, oB);

        // per-subspace code -> scratch (no cross-warp sync needed)
        if (L == 0) g_codes[s][t] = kmin;
    }

    // reduce loss within warp; one non-atomic partial per warp
    #pragma unroll
    for (int m = 16; m >= 1; m >>= 1) errAcc += __shfl_xor_sync(FULL, errAcc, m);
    if (L == 0) g_partials[blockIdx.x * 4 + w] = errAcc;
}

// Pack ids (4 subspace codes -> packed int as float) and finalize vq loss.
__global__ __launch_bounds__(256) void dvq_pack_kernel(float* __restrict__ out) {
    const int i = blockIdx.x * 256 + threadIdx.x;   // grid covers TOK exactly
    const int packed = g_codes[0][i] + 16 * g_codes[1][i]
                     + 256 * g_codes[2][i] + 4096 * g_codes[3][i];
    out[IDOFF + i] = (float)packed;

    if (blockIdx.x == 0) {
        __shared__ float red[256];
        float a = 0.0f;
        for (int j = threadIdx.x; j < NB * 4; j += 256) a += g_partials[j];
        red[threadIdx.x] = a;
        __syncthreads();
        for (int st = 128; st > 0; st >>= 1) {
            if (threadIdx.x < st) red[threadIdx.x] += red[threadIdx.x + st];
            __syncthreads();
        }
        // vq_total = (1 + BETA) * sum_sq / (B*N*d); BETA=0.25, B*N*d = 8388608
        if (threadIdx.x == 0) out[VQOFF] = red[0] * (1.25f / 8388608.0f);
    }
}

extern "C" void kernel_launch(void* const* d_in, const int* in_sizes, int n_in,
                              void* d_out, int out_size) {
    const float* h  = (const float*)d_in[0];
    const float* cb = (const float*)d_in[1];
    float* out = (float*)d_out;

    cudaFuncSetAttribute(dvq_kernel, cudaFuncAttributeMaxDynamicSharedMemorySize, 65536);

    dvq_kernel<<<NB, 128, 65536>>>(h, cb, out, NB);
    dvq_pack_kernel<<<TOK / 256, 256>>>(out);
}